// round 1
// baseline (speedup 1.0000x reference)
#include <cuda_runtime.h>
#include <cuda_bf16.h>
#include <math.h>

// ---------------- problem constants ----------------
#define BB     32
#define LL     4096
#define PP     16
#define NPATCH 256           // L / P
#define SS     257           // NPATCH + 1
#define DD     512
#define HH     8
#define DHD    64
#define NLAYER 8
#define FFD    2048
#define NCLS   4
#define MTOK   (BB*SS)       // 8224
#define MPATCH (BB*NPATCH)   // 8192
#define KCONV  (PP*DD)       // 8192

// ---------------- scratch (device globals; no allocation) ----------------
__device__ float g_x[MTOK*DD];
__device__ float g_q[MTOK*DD];
__device__ float g_k[MTOK*DD];
__device__ float g_v[MTOK*DD];
__device__ float g_attn[MTOK*DD];
__device__ float g_h[MTOK*FFD];
__device__ float g_y[MPATCH*DD];
__device__ float g_xe[(size_t)MPATCH*KCONV];
__device__ float g_wct[(size_t)KCONV*DD];
__device__ float g_kv[BB*HH*DHD*DHD];
__device__ float g_ksum[BB*HH*DHD];
__device__ float g_z[MTOK*HH];
__device__ float g_len[BB];

// ---------------- SGEMM: C = A(MxK) @ B(KxN) + bias [+ res] [gelu] ----------------
// EPI: 0 = bias only, 1 = bias+gelu, 2 = bias+residual
#define BM 128
#define BN 128
#define BK 8
#define TM 8
#define TN 8

template<int EPI>
__global__ __launch_bounds__(256)
void sgemm_kernel(const float* __restrict__ A, const float* __restrict__ B,
                  const float* __restrict__ bias, const float* __restrict__ res,
                  float* __restrict__ C, int M, int N, int K)
{
    __shared__ float As[BK][BM];
    __shared__ float Bs[BK][BN];
    const int tid = threadIdx.x;
    const int row0 = blockIdx.y * BM;
    const int col0 = blockIdx.x * BN;

    const int aRow = tid >> 1;          // 0..127
    const int aCol = (tid & 1) * 4;     // 0 or 4
    const int bRow = tid >> 5;          // 0..7
    const int bCol = (tid & 31) * 4;    // 0..124

    const int ty = tid >> 4;            // 0..15
    const int tx = tid & 15;            // 0..15
    const int cr = ty * TM;
    const int cc = tx * TN;

    float acc[TM][TN];
    #pragma unroll
    for (int i = 0; i < TM; i++)
        #pragma unroll
        for (int j = 0; j < TN; j++) acc[i][j] = 0.f;

    for (int k0 = 0; k0 < K; k0 += BK) {
        float4 av = make_float4(0.f, 0.f, 0.f, 0.f);
        if (row0 + aRow < M)
            av = *(const float4*)(A + (size_t)(row0 + aRow) * K + k0 + aCol);
        As[aCol + 0][aRow] = av.x;
        As[aCol + 1][aRow] = av.y;
        As[aCol + 2][aRow] = av.z;
        As[aCol + 3][aRow] = av.w;

        float4 bv = *(const float4*)(B + (size_t)(k0 + bRow) * N + col0 + bCol);
        *(float4*)(&Bs[bRow][bCol]) = bv;
        __syncthreads();

        #pragma unroll
        for (int kk = 0; kk < BK; kk++) {
            float ar[TM], br[TN];
            float4 a0 = *(const float4*)(&As[kk][cr]);
            float4 a1 = *(const float4*)(&As[kk][cr + 4]);
            ar[0]=a0.x; ar[1]=a0.y; ar[2]=a0.z; ar[3]=a0.w;
            ar[4]=a1.x; ar[5]=a1.y; ar[6]=a1.z; ar[7]=a1.w;
            float4 b0 = *(const float4*)(&Bs[kk][cc]);
            float4 b1 = *(const float4*)(&Bs[kk][cc + 4]);
            br[0]=b0.x; br[1]=b0.y; br[2]=b0.z; br[3]=b0.w;
            br[4]=b1.x; br[5]=b1.y; br[6]=b1.z; br[7]=b1.w;
            #pragma unroll
            for (int i = 0; i < TM; i++)
                #pragma unroll
                for (int j = 0; j < TN; j++)
                    acc[i][j] = fmaf(ar[i], br[j], acc[i][j]);
        }
        __syncthreads();
    }

    #pragma unroll
    for (int i = 0; i < TM; i++) {
        int r = row0 + cr + i;
        if (r >= M) break;
        #pragma unroll
        for (int j = 0; j < TN; j++) {
            int c = col0 + cc + j;
            float v = acc[i][j] + bias[c];
            if (EPI == 1) {
                v = 0.5f * v * (1.f + erff(v * 0.70710678118654752f));
            } else if (EPI == 2) {
                v += res[(size_t)r * N + c];
            }
            C[(size_t)r * N + c] = v;
        }
    }
}

// ---------------- conv_w transpose: wct[p*D+i][o] = conv_w[o][i][p] ----------------
__global__ void transpose_convw_kernel(const float* __restrict__ cw, float* __restrict__ wct)
{
    size_t idx = (size_t)blockIdx.x * blockDim.x + threadIdx.x;
    if (idx >= (size_t)KCONV * DD) return;
    int k = (int)(idx >> 9);        // 0..8191  (k index)
    int o = (int)(idx & 511);
    int p = k >> 9;                 // k / 512
    int i = k & 511;
    wct[idx] = cw[(size_t)o * (DD * PP) + i * PP + p];
}

// ---------------- gather embeddings: xe[m][p*512+i] = emb[tok][i] ----------------
__global__ void gather_emb_kernel(const int* __restrict__ inp, const float* __restrict__ emb,
                                  float* __restrict__ xe)
{
    size_t idx = (size_t)blockIdx.x * blockDim.x + threadIdx.x;
    if (idx >= (size_t)MPATCH * KCONV) return;
    int m = (int)(idx >> 13);       // / 8192
    int k = (int)(idx & 8191);
    int p = k >> 9;
    int i = k & 511;
    int b = m >> 8;                 // / 256
    int j = m & 255;
    int t = inp[b * LL + j * PP + p];
    xe[idx] = emb[(size_t)t * DD + i];
}

// ---------------- assemble x: cls at s=0, conv out + pos otherwise ----------------
__global__ void assemble_x_kernel(const float* __restrict__ y, const float* __restrict__ cls,
                                  const float* __restrict__ pos, float* __restrict__ x)
{
    size_t idx = (size_t)blockIdx.x * blockDim.x + threadIdx.x;
    if (idx >= (size_t)MTOK * DD) return;
    int r = (int)(idx >> 9);
    int o = (int)(idx & 511);
    int b = r / SS;
    int s = r - b * SS;
    float v;
    if (s == 0) v = cls[o];
    else        v = y[(size_t)(b * NPATCH + (s - 1)) * DD + o];
    x[idx] = v + pos[(size_t)s * DD + o];
}

// ---------------- lengths ----------------
__global__ void lengths_kernel(const float* __restrict__ mask, float* __restrict__ len)
{
    __shared__ float red[256];
    int b = blockIdx.x;
    float s = 0.f;
    for (int i = threadIdx.x; i < LL; i += 256) s += mask[(size_t)b * LL + i];
    red[threadIdx.x] = s; __syncthreads();
    for (int st = 128; st > 0; st >>= 1) {
        if (threadIdx.x < st) red[threadIdx.x] += red[threadIdx.x + st];
        __syncthreads();
    }
    if (threadIdx.x == 0) len[b] = ceilf((red[0] + 1.0f) / (float)PP);
}

// ---------------- RoPE + feature map (elu+1), in-place on q and k ----------------
__device__ __forceinline__ float elu1(float x) { return x > 0.f ? x + 1.f : __expf(x); }

__global__ void rope_feat_kernel(float* __restrict__ q, float* __restrict__ k,
                                 const float* __restrict__ len)
{
    size_t idx = (size_t)blockIdx.x * blockDim.x + threadIdx.x;
    if (idx >= (size_t)MTOK * HH * 32) return;
    int m   = (int)(idx >> 8);      // token index
    int rem = (int)(idx & 255);
    int h = rem >> 5;
    int d = rem & 31;
    int b = m / SS;
    int s = m - b * SS;
    float inv = expf(-logf(10000.f) * (float)d / 32.f);
    float ang = (float)s * inv;
    float c, sn;
    sincosf(ang, &sn, &c);
    size_t base = (size_t)m * DD + h * DHD + d;
    float q1 = q[base], q2 = q[base + 32];
    q[base]      = elu1(q1 * c - q2 * sn);
    q[base + 32] = elu1(q2 * c + q1 * sn);
    float lm = ((float)s < len[b]) ? 1.f : 0.f;
    float k1 = k[base], k2 = k[base + 32];
    k[base]      = elu1(k1 * c - k2 * sn) * lm;
    k[base + 32] = elu1(k2 * c + k1 * sn) * lm;
}

// ---------------- kv[b,h,d,m] and ksum[b,h,d] ----------------
__global__ __launch_bounds__(256)
void kv_ksum_kernel(const float* __restrict__ kf, const float* __restrict__ v,
                    float* __restrict__ kv, float* __restrict__ ksum)
{
    int bh = blockIdx.x;
    int b = bh >> 3, h = bh & 7;
    __shared__ float ks[8][64], vs[8][64];
    int tid = threadIdx.x;
    int d  = tid >> 2;
    int m0 = (tid & 3) << 4;
    float acc[16];
    #pragma unroll
    for (int j = 0; j < 16; j++) acc[j] = 0.f;
    float sacc = 0.f;

    for (int s0 = 0; s0 < SS; s0 += 8) {
        #pragma unroll
        for (int qq = 0; qq < 2; qq++) {
            int li = tid + qq * 256;
            int r = li >> 6, c = li & 63;
            int s = s0 + r;
            float kval = 0.f, vval = 0.f;
            if (s < SS) {
                size_t off = (size_t)(b * SS + s) * DD + h * DHD + c;
                kval = kf[off]; vval = v[off];
            }
            ks[r][c] = kval; vs[r][c] = vval;
        }
        __syncthreads();
        #pragma unroll
        for (int r = 0; r < 8; r++) {
            float kd = ks[r][d];
            if ((tid & 3) == 0) sacc += kd;
            #pragma unroll
            for (int j = 0; j < 16; j++)
                acc[j] = fmaf(kd, vs[r][m0 + j], acc[j]);
        }
        __syncthreads();
    }
    float* out = kv + (size_t)bh * (DHD * DHD) + d * DHD + m0;
    #pragma unroll
    for (int j = 0; j < 16; j++) out[j] = acc[j];
    if ((tid & 3) == 0) ksum[bh * DHD + d] = sacc;
}

// ---------------- z[b,s,h] = 1/(qf . ksum + 1e-6), warp per (token,head) ----------------
__global__ void z_kernel(const float* __restrict__ qf, const float* __restrict__ ksum,
                         float* __restrict__ z)
{
    int gtid = blockIdx.x * blockDim.x + threadIdx.x;
    int wid = gtid >> 5;
    int lane = threadIdx.x & 31;
    if (wid >= MTOK * HH) return;
    int h = wid & 7;
    int m = wid >> 3;
    int b = m / SS;
    const float* qrow = qf + (size_t)m * DD + h * DHD;
    const float* ks = ksum + (b * HH + h) * DHD;
    float p = qrow[lane] * ks[lane] + qrow[lane + 32] * ks[lane + 32];
    #pragma unroll
    for (int o = 16; o > 0; o >>= 1) p += __shfl_xor_sync(0xffffffffu, p, o);
    if (lane == 0) z[wid] = 1.f / (p + 1e-6f);
}

// ---------------- attn[b,s,h,m] = z * qf @ kv ----------------
__global__ __launch_bounds__(256)
void attn_kernel(const float* __restrict__ qf, const float* __restrict__ kv,
                 const float* __restrict__ z, float* __restrict__ attn)
{
    int bh = blockIdx.x;
    int b = bh >> 3, h = bh & 7;
    __shared__ float kvs[64][64];
    __shared__ float qs[4][64];
    __shared__ float zs[4];
    int tid = threadIdx.x;
    #pragma unroll
    for (int qq = 0; qq < 16; qq++)
        ((float*)kvs)[tid + qq * 256] = kv[(size_t)bh * (DHD * DHD) + tid + qq * 256];
    __syncthreads();
    int r = tid >> 6, c = tid & 63;
    for (int s0 = 0; s0 < SS; s0 += 4) {
        int s = s0 + r;
        if (s < SS) qs[r][c] = qf[(size_t)(b * SS + s) * DD + h * DHD + c];
        if (tid < 4 && (s0 + tid) < SS) zs[tid] = z[(b * SS + s0 + tid) * HH + h];
        __syncthreads();
        if (s < SS) {
            float acc = 0.f;
            #pragma unroll
            for (int d = 0; d < 64; d++) acc = fmaf(qs[r][d], kvs[d][c], acc);
            attn[(size_t)(b * SS + s) * DD + h * DHD + c] = acc * zs[r];
        }
        __syncthreads();
    }
}

// ---------------- layernorm in place, one block per row ----------------
__global__ __launch_bounds__(256)
void ln_kernel(float* __restrict__ x, const float* __restrict__ sc, const float* __restrict__ bi)
{
    int row = blockIdx.x;
    int tid = threadIdx.x;
    float* xr = x + (size_t)row * DD;
    float a = xr[tid], b = xr[tid + 256];
    __shared__ float s1[256], s2[256];
    s1[tid] = a + b;
    s2[tid] = a * a + b * b;
    __syncthreads();
    for (int st = 128; st > 0; st >>= 1) {
        if (tid < st) { s1[tid] += s1[tid + st]; s2[tid] += s2[tid + st]; }
        __syncthreads();
    }
    float mean = s1[0] * (1.f / DD);
    float var = s2[0] * (1.f / DD) - mean * mean;
    float inv = rsqrtf(var + 1e-5f);
    xr[tid]       = (a - mean) * inv * sc[tid] + bi[tid];
    xr[tid + 256] = (b - mean) * inv * sc[tid + 256] + bi[tid + 256];
}

// ---------------- classifier head: out[b,c] = x[b,0,:] @ out_w + out_b ----------------
__global__ void head_kernel(const float* __restrict__ x, const float* __restrict__ w,
                            const float* __restrict__ bias, float* __restrict__ out)
{
    int t = threadIdx.x;
    if (t >= BB * NCLS) return;
    int b = t >> 2, c = t & 3;
    const float* xr = x + (size_t)(b * SS) * DD;
    float acc = 0.f;
    for (int k = 0; k < DD; k++) acc = fmaf(xr[k], w[k * NCLS + c], acc);
    out[t] = acc + bias[c];
}

// ---------------- host driver ----------------
static void launch_gemm(int epi, const float* A, const float* B, const float* bias,
                        const float* res, float* C, int M, int N, int K)
{
    dim3 grid(N / BN, (M + BM - 1) / BM);
    if (epi == 0)      sgemm_kernel<0><<<grid, 256>>>(A, B, bias, res, C, M, N, K);
    else if (epi == 1) sgemm_kernel<1><<<grid, 256>>>(A, B, bias, res, C, M, N, K);
    else               sgemm_kernel<2><<<grid, 256>>>(A, B, bias, res, C, M, N, K);
}

extern "C" void kernel_launch(void* const* d_in, const int* in_sizes, int n_in,
                              void* d_out, int out_size)
{
    const int*   inputs     = (const int*)  d_in[0];
    const float* input_mask = (const float*)d_in[1];
    const float* emb        = (const float*)d_in[2];
    const float* conv_w     = (const float*)d_in[3];
    const float* conv_b     = (const float*)d_in[4];
    const float* pos        = (const float*)d_in[5];
    const float* cls        = (const float*)d_in[6];
    const float* Wq         = (const float*)d_in[7];
    const float* bq         = (const float*)d_in[8];
    const float* Wk         = (const float*)d_in[9];
    const float* bk         = (const float*)d_in[10];
    const float* Wv         = (const float*)d_in[11];
    const float* bv         = (const float*)d_in[12];
    const float* Wo         = (const float*)d_in[13];
    const float* bo         = (const float*)d_in[14];
    const float* ln1_s      = (const float*)d_in[15];
    const float* ln1_b      = (const float*)d_in[16];
    const float* ln2_s      = (const float*)d_in[17];
    const float* ln2_b      = (const float*)d_in[18];
    const float* W1         = (const float*)d_in[19];
    const float* b1         = (const float*)d_in[20];
    const float* W2         = (const float*)d_in[21];
    const float* b2         = (const float*)d_in[22];
    const float* lnf_s      = (const float*)d_in[23];
    const float* lnf_b      = (const float*)d_in[24];
    const float* out_w      = (const float*)d_in[25];
    const float* out_b      = (const float*)d_in[26];
    float* out              = (float*)d_out;

    float *x, *q, *k, *v, *attn, *hbuf, *ybuf, *xe, *wct, *kv, *ksum, *z, *len;
    cudaGetSymbolAddress((void**)&x,    g_x);
    cudaGetSymbolAddress((void**)&q,    g_q);
    cudaGetSymbolAddress((void**)&k,    g_k);
    cudaGetSymbolAddress((void**)&v,    g_v);
    cudaGetSymbolAddress((void**)&attn, g_attn);
    cudaGetSymbolAddress((void**)&hbuf, g_h);
    cudaGetSymbolAddress((void**)&ybuf, g_y);
    cudaGetSymbolAddress((void**)&xe,   g_xe);
    cudaGetSymbolAddress((void**)&wct,  g_wct);
    cudaGetSymbolAddress((void**)&kv,   g_kv);
    cudaGetSymbolAddress((void**)&ksum, g_ksum);
    cudaGetSymbolAddress((void**)&z,    g_z);
    cudaGetSymbolAddress((void**)&len,  g_len);

    // ---- embedding conv ----
    {
        size_t n1 = (size_t)KCONV * DD;
        transpose_convw_kernel<<<(unsigned)((n1 + 255) / 256), 256>>>(conv_w, wct);
        size_t n2 = (size_t)MPATCH * KCONV;
        gather_emb_kernel<<<(unsigned)((n2 + 255) / 256), 256>>>(inputs, emb, xe);
        launch_gemm(0, xe, wct, conv_b, nullptr, ybuf, MPATCH, DD, KCONV);
        size_t n3 = (size_t)MTOK * DD;
        assemble_x_kernel<<<(unsigned)((n3 + 255) / 256), 256>>>(ybuf, cls, pos, x);
        lengths_kernel<<<BB, 256>>>(input_mask, len);
    }

    // ---- transformer layers ----
    for (int i = 0; i < NLAYER; i++) {
        const float* Wqi = Wq + (size_t)i * DD * DD;
        const float* Wki = Wk + (size_t)i * DD * DD;
        const float* Wvi = Wv + (size_t)i * DD * DD;
        const float* Woi = Wo + (size_t)i * DD * DD;
        const float* W1i = W1 + (size_t)i * DD * FFD;
        const float* W2i = W2 + (size_t)i * FFD * DD;

        launch_gemm(0, x, Wqi, bq + i * DD, nullptr, q, MTOK, DD, DD);
        launch_gemm(0, x, Wki, bk + i * DD, nullptr, k, MTOK, DD, DD);
        launch_gemm(0, x, Wvi, bv + i * DD, nullptr, v, MTOK, DD, DD);

        {
            size_t n = (size_t)MTOK * HH * 32;
            rope_feat_kernel<<<(unsigned)((n + 255) / 256), 256>>>(q, k, len);
        }
        kv_ksum_kernel<<<BB * HH, 256>>>(k, v, kv, ksum);
        {
            size_t n = (size_t)MTOK * HH * 32;
            z_kernel<<<(unsigned)((n + 255) / 256), 256>>>(q, ksum, z);
        }
        attn_kernel<<<BB * HH, 256>>>(q, kv, z, attn);

        launch_gemm(2, attn, Woi, bo + i * DD, x, x, MTOK, DD, DD);
        ln_kernel<<<MTOK, 256>>>(x, ln1_s + i * DD, ln1_b + i * DD);

        launch_gemm(1, x, W1i, b1 + i * FFD, nullptr, hbuf, MTOK, FFD, DD);
        launch_gemm(2, hbuf, W2i, b2 + i * DD, x, x, MTOK, DD, FFD);
        ln_kernel<<<MTOK, 256>>>(x, ln2_s + i * DD, ln2_b + i * DD);
    }

    // ---- final LN + head ----
    ln_kernel<<<MTOK, 256>>>(x, lnf_s, lnf_b);
    head_kernel<<<1, 128>>>(x, out_w, out_b, out);
}

// round 2
// speedup vs baseline: 1.5951x; 1.5951x over previous
#include <cuda_runtime.h>
#include <cuda_bf16.h>
#include <mma.h>
#include <math.h>

using namespace nvcuda;

// ---------------- problem constants ----------------
#define BB     32
#define LL     4096
#define PP     16
#define NPATCH 256           // L / P
#define SS     257           // NPATCH + 1
#define DD     512
#define HH     8
#define DHD    64
#define NLAYER 8
#define FFD    2048
#define NCLS   4
#define MTOK   (BB*SS)       // 8224
#define MPAD   8320          // 65 * 128  (padded token rows)
#define MPATCH (BB*NPATCH)   // 8192
#define KCONV  (PP*DD)       // 8192

// ---------------- scratch (device globals; zero-initialized, no allocation) ----------------
__device__ float g_x[MPAD*DD];
__device__ float g_q[MPAD*DD];
__device__ float g_k[MPAD*DD];
__device__ float g_v[MPAD*DD];
__device__ float g_t[MPAD*DD];
__device__ float g_h[(size_t)MPAD*FFD];
__device__ float g_y[MPATCH*DD];
__device__ float g_wct[(size_t)KCONV*DD];
__device__ float g_kv[BB*HH*DHD*DHD];
__device__ float g_ksum[BB*HH*DHD];
__device__ float g_z[MTOK*HH];
__device__ float g_len[BB];

// ---------------- tf32 WMMA GEMM: C = f(A) @ B (no epilogue) ----------------
// AMODE: 0 = plain, 1 = gelu(A + abias[k]) on load, 2 = embedding gather
#define BM 128
#define BN 128
#define BKK 32
#define AS_STRIDE (BKK + 4)    // 36 floats = 144B (16B multiple)
#define BS_STRIDE (BN + 4)     // 132 floats = 528B (16B multiple)

__device__ __forceinline__ float gelu_exact(float v)
{
    return 0.5f * v * (1.f + erff(v * 0.70710678118654752f));
}

template<int AMODE>
__global__ __launch_bounds__(256, 2)
void gemm_tf32(const float* __restrict__ A, const float* __restrict__ B,
               float* __restrict__ C, int M, int N, int K,
               const float* __restrict__ abias,
               const int* __restrict__ gidx, const float* __restrict__ gtab)
{
    __shared__ float As[BM][AS_STRIDE];
    __shared__ float Bs[BKK][BS_STRIDE];

    const int tid = threadIdx.x;
    const int wid = tid >> 5;
    const int warp_row = wid >> 2;      // 0..1  -> 64 rows each
    const int warp_col = wid & 3;       // 0..3  -> 32 cols each
    const int row0 = blockIdx.y * BM;
    const int col0 = blockIdx.x * BN;

    wmma::fragment<wmma::accumulator, 16, 16, 8, float> acc[4][2];
    #pragma unroll
    for (int mi = 0; mi < 4; mi++)
        #pragma unroll
        for (int ni = 0; ni < 2; ni++)
            wmma::fill_fragment(acc[mi][ni], 0.f);

    const int a_c4 = (tid & 7) * 4;     // 0..28
    const int a_r  = tid >> 3;          // 0..31
    const int b_c4 = (tid & 31) * 4;    // 0..124
    const int b_r  = tid >> 5;          // 0..7

    for (int k0 = 0; k0 < K; k0 += BKK) {
        // ---- load A tile (128 x 32) ----
        #pragma unroll
        for (int it = 0; it < 4; it++) {
            int r = a_r + it * 32;
            int grow = row0 + r;
            int gk = k0 + a_c4;
            float4 av;
            if (AMODE == 2) {
                int bb = grow >> 8;             // / 256
                int jj = grow & 255;
                int p  = gk >> 9;               // / 512
                int ii = gk & 511;
                int tok = gidx[bb * LL + jj * PP + p];
                av = *(const float4*)(gtab + (size_t)tok * DD + ii);
            } else {
                av = *(const float4*)(A + (size_t)grow * K + gk);
                if (AMODE == 1) {
                    float4 bsv = *(const float4*)(abias + gk);
                    av.x = gelu_exact(av.x + bsv.x);
                    av.y = gelu_exact(av.y + bsv.y);
                    av.z = gelu_exact(av.z + bsv.z);
                    av.w = gelu_exact(av.w + bsv.w);
                }
            }
            *(float4*)(&As[r][a_c4]) = av;
        }
        // ---- load B tile (32 x 128) ----
        #pragma unroll
        for (int it = 0; it < 4; it++) {
            int r = b_r + it * 8;
            *(float4*)(&Bs[r][b_c4]) =
                *(const float4*)(B + (size_t)(k0 + r) * N + col0 + b_c4);
        }
        __syncthreads();

        #pragma unroll
        for (int kk = 0; kk < BKK; kk += 8) {
            wmma::fragment<wmma::matrix_a, 16, 16, 8, wmma::precision::tf32, wmma::row_major> af[4];
            wmma::fragment<wmma::matrix_b, 16, 16, 8, wmma::precision::tf32, wmma::row_major> bf[2];
            #pragma unroll
            for (int mi = 0; mi < 4; mi++) {
                wmma::load_matrix_sync(af[mi], &As[warp_row * 64 + mi * 16][kk], AS_STRIDE);
                #pragma unroll
                for (int t = 0; t < af[mi].num_elements; t++)
                    af[mi].x[t] = wmma::__float_to_tf32(af[mi].x[t]);
            }
            #pragma unroll
            for (int ni = 0; ni < 2; ni++) {
                wmma::load_matrix_sync(bf[ni], &Bs[kk][warp_col * 32 + ni * 16], BS_STRIDE);
                #pragma unroll
                for (int t = 0; t < bf[ni].num_elements; t++)
                    bf[ni].x[t] = wmma::__float_to_tf32(bf[ni].x[t]);
            }
            #pragma unroll
            for (int mi = 0; mi < 4; mi++)
                #pragma unroll
                for (int ni = 0; ni < 2; ni++)
                    wmma::mma_sync(acc[mi][ni], af[mi], bf[ni], acc[mi][ni]);
        }
        __syncthreads();
    }

    #pragma unroll
    for (int mi = 0; mi < 4; mi++)
        #pragma unroll
        for (int ni = 0; ni < 2; ni++)
            wmma::store_matrix_sync(
                C + (size_t)(row0 + warp_row * 64 + mi * 16) * N + col0 + warp_col * 32 + ni * 16,
                acc[mi][ni], N, wmma::mem_row_major);
}

// ---------------- conv_w transpose: wct[p*D+i][o] = conv_w[o][i][p] ----------------
__global__ void transpose_convw_kernel(const float* __restrict__ cw, float* __restrict__ wct)
{
    size_t idx = (size_t)blockIdx.x * blockDim.x + threadIdx.x;
    if (idx >= (size_t)KCONV * DD) return;
    int k = (int)(idx >> 9);
    int o = (int)(idx & 511);
    int p = k >> 9;
    int i = k & 511;
    wct[idx] = cw[(size_t)o * (DD * PP) + i * PP + p];
}

// ---------------- assemble x: cls at s=0, conv out + conv_b otherwise; +pos ----------------
__global__ void assemble_x_kernel(const float* __restrict__ y, const float* __restrict__ cls,
                                  const float* __restrict__ pos, const float* __restrict__ cb,
                                  float* __restrict__ x)
{
    size_t idx = (size_t)blockIdx.x * blockDim.x + threadIdx.x;
    if (idx >= (size_t)MTOK * DD) return;
    int r = (int)(idx >> 9);
    int o = (int)(idx & 511);
    int b = r / SS;
    int s = r - b * SS;
    float v;
    if (s == 0) v = cls[o];
    else        v = y[(size_t)(b * NPATCH + (s - 1)) * DD + o] + cb[o];
    x[(size_t)r * DD + o] = v + pos[(size_t)s * DD + o];
}

// ---------------- lengths ----------------
__global__ void lengths_kernel(const float* __restrict__ mask, float* __restrict__ len)
{
    __shared__ float red[256];
    int b = blockIdx.x;
    float s = 0.f;
    for (int i = threadIdx.x; i < LL; i += 256) s += mask[(size_t)b * LL + i];
    red[threadIdx.x] = s; __syncthreads();
    for (int st = 128; st > 0; st >>= 1) {
        if (threadIdx.x < st) red[threadIdx.x] += red[threadIdx.x + st];
        __syncthreads();
    }
    if (threadIdx.x == 0) len[b] = ceilf((red[0] + 1.0f) / (float)PP);
}

// ---------------- RoPE + qkv bias + feature map (elu+1), in-place on q and k ----------------
__device__ __forceinline__ float elu1(float x) { return x > 0.f ? x + 1.f : __expf(x); }

__global__ void rope_feat_kernel(float* __restrict__ q, float* __restrict__ k,
                                 const float* __restrict__ bq, const float* __restrict__ bk,
                                 const float* __restrict__ len)
{
    size_t idx = (size_t)blockIdx.x * blockDim.x + threadIdx.x;
    if (idx >= (size_t)MTOK * HH * 32) return;
    int m   = (int)(idx >> 8);
    int rem = (int)(idx & 255);
    int h = rem >> 5;
    int d = rem & 31;
    int b = m / SS;
    int s = m - b * SS;
    float inv = expf(-logf(10000.f) * (float)d / 32.f);
    float ang = (float)s * inv;
    float c, sn;
    sincosf(ang, &sn, &c);
    size_t base = (size_t)m * DD + h * DHD + d;
    int bi = h * DHD + d;
    float q1 = q[base] + bq[bi], q2 = q[base + 32] + bq[bi + 32];
    q[base]      = elu1(q1 * c - q2 * sn);
    q[base + 32] = elu1(q2 * c + q1 * sn);
    float lm = ((float)s < len[b]) ? 1.f : 0.f;
    float k1 = k[base] + bk[bi], k2 = k[base + 32] + bk[bi + 32];
    k[base]      = elu1(k1 * c - k2 * sn) * lm;
    k[base + 32] = elu1(k2 * c + k1 * sn) * lm;
}

// ---------------- kv[b,h,d,m] and ksum[b,h,d]; adds v bias ----------------
__global__ __launch_bounds__(256)
void kv_ksum_kernel(const float* __restrict__ kf, const float* __restrict__ v,
                    const float* __restrict__ bv,
                    float* __restrict__ kv, float* __restrict__ ksum)
{
    int bh = blockIdx.x;
    int b = bh >> 3, h = bh & 7;
    __shared__ float ks[8][64], vs[8][64];
    int tid = threadIdx.x;
    int d  = tid >> 2;
    int m0 = (tid & 3) << 4;
    float acc[16];
    #pragma unroll
    for (int j = 0; j < 16; j++) acc[j] = 0.f;
    float sacc = 0.f;

    for (int s0 = 0; s0 < SS; s0 += 8) {
        #pragma unroll
        for (int qq = 0; qq < 2; qq++) {
            int li = tid + qq * 256;
            int r = li >> 6, c = li & 63;
            int s = s0 + r;
            float kval = 0.f, vval = 0.f;
            if (s < SS) {
                size_t off = (size_t)(b * SS + s) * DD + h * DHD + c;
                kval = kf[off]; vval = v[off] + bv[h * DHD + c];
            }
            ks[r][c] = kval; vs[r][c] = vval;
        }
        __syncthreads();
        #pragma unroll
        for (int r = 0; r < 8; r++) {
            float kd = ks[r][d];
            if ((tid & 3) == 0) sacc += kd;
            #pragma unroll
            for (int j = 0; j < 16; j++)
                acc[j] = fmaf(kd, vs[r][m0 + j], acc[j]);
        }
        __syncthreads();
    }
    float* out = kv + (size_t)bh * (DHD * DHD) + d * DHD + m0;
    #pragma unroll
    for (int j = 0; j < 16; j++) out[j] = acc[j];
    if ((tid & 3) == 0) ksum[bh * DHD + d] = sacc;
}

// ---------------- z[b,s,h] = 1/(qf . ksum + 1e-6), warp per (token,head) ----------------
__global__ void z_kernel(const float* __restrict__ qf, const float* __restrict__ ksum,
                         float* __restrict__ z)
{
    int gtid = blockIdx.x * blockDim.x + threadIdx.x;
    int wid = gtid >> 5;
    int lane = threadIdx.x & 31;
    if (wid >= MTOK * HH) return;
    int h = wid & 7;
    int m = wid >> 3;
    int b = m / SS;
    const float* qrow = qf + (size_t)m * DD + h * DHD;
    const float* ks = ksum + (b * HH + h) * DHD;
    float p = qrow[lane] * ks[lane] + qrow[lane + 32] * ks[lane + 32];
    #pragma unroll
    for (int o = 16; o > 0; o >>= 1) p += __shfl_xor_sync(0xffffffffu, p, o);
    if (lane == 0) z[wid] = 1.f / (p + 1e-6f);
}

// ---------------- attn[b,s,h,m] = z * qf @ kv ----------------
__global__ __launch_bounds__(256)
void attn_kernel(const float* __restrict__ qf, const float* __restrict__ kv,
                 const float* __restrict__ z, float* __restrict__ attn)
{
    int bh = blockIdx.x;
    int b = bh >> 3, h = bh & 7;
    __shared__ float kvs[64][64];
    __shared__ float qs[4][64];
    __shared__ float zs[4];
    int tid = threadIdx.x;
    #pragma unroll
    for (int qq = 0; qq < 16; qq++)
        ((float*)kvs)[tid + qq * 256] = kv[(size_t)bh * (DHD * DHD) + tid + qq * 256];
    __syncthreads();
    int r = tid >> 6, c = tid & 63;
    for (int s0 = 0; s0 < SS; s0 += 4) {
        int s = s0 + r;
        if (s < SS) qs[r][c] = qf[(size_t)(b * SS + s) * DD + h * DHD + c];
        if (tid < 4 && (s0 + tid) < SS) zs[tid] = z[(b * SS + s0 + tid) * HH + h];
        __syncthreads();
        if (s < SS) {
            float acc = 0.f;
            #pragma unroll
            for (int d = 0; d < 64; d++) acc = fmaf(qs[r][d], kvs[d][c], acc);
            attn[(size_t)(b * SS + s) * DD + h * DHD + c] = acc * zs[r];
        }
        __syncthreads();
    }
}

// ---------------- layernorm; FUSE: x = LN(x + t + bias), else x = LN(x) ----------------
template<bool FUSE>
__global__ __launch_bounds__(256)
void ln_kernel(const float* __restrict__ t, const float* __restrict__ bias,
               float* __restrict__ x, const float* __restrict__ sc, const float* __restrict__ bi)
{
    int row = blockIdx.x;
    int tid = threadIdx.x;
    float* xr = x + (size_t)row * DD;
    float a, b;
    if (FUSE) {
        const float* tr = t + (size_t)row * DD;
        a = xr[tid]       + tr[tid]       + bias[tid];
        b = xr[tid + 256] + tr[tid + 256] + bias[tid + 256];
    } else {
        a = xr[tid]; b = xr[tid + 256];
    }
    __shared__ float s1[256], s2[256];
    s1[tid] = a + b;
    s2[tid] = a * a + b * b;
    __syncthreads();
    for (int st = 128; st > 0; st >>= 1) {
        if (tid < st) { s1[tid] += s1[tid + st]; s2[tid] += s2[tid + st]; }
        __syncthreads();
    }
    float mean = s1[0] * (1.f / DD);
    float var = s2[0] * (1.f / DD) - mean * mean;
    float inv = rsqrtf(var + 1e-5f);
    xr[tid]       = (a - mean) * inv * sc[tid] + bi[tid];
    xr[tid + 256] = (b - mean) * inv * sc[tid + 256] + bi[tid + 256];
}

// ---------------- classifier head ----------------
__global__ void head_kernel(const float* __restrict__ x, const float* __restrict__ w,
                            const float* __restrict__ bias, float* __restrict__ out)
{
    int t = threadIdx.x;
    if (t >= BB * NCLS) return;
    int b = t >> 2, c = t & 3;
    const float* xr = x + (size_t)(b * SS) * DD;
    float acc = 0.f;
    for (int k = 0; k < DD; k++) acc = fmaf(xr[k], w[k * NCLS + c], acc);
    out[t] = acc + bias[c];
}

// ---------------- host driver ----------------
static void launch_gemm_plain(const float* A, const float* B, float* C, int M, int N, int K)
{
    dim3 grid(N / BN, M / BM);
    gemm_tf32<0><<<grid, 256>>>(A, B, C, M, N, K, nullptr, nullptr, nullptr);
}
static void launch_gemm_gelu(const float* A, const float* B, float* C, int M, int N, int K,
                             const float* abias)
{
    dim3 grid(N / BN, M / BM);
    gemm_tf32<1><<<grid, 256>>>(A, B, C, M, N, K, abias, nullptr, nullptr);
}
static void launch_gemm_gather(const int* gidx, const float* gtab, const float* B, float* C,
                               int M, int N, int K)
{
    dim3 grid(N / BN, M / BM);
    gemm_tf32<2><<<grid, 256>>>(nullptr, B, C, M, N, K, nullptr, gidx, gtab);
}

extern "C" void kernel_launch(void* const* d_in, const int* in_sizes, int n_in,
                              void* d_out, int out_size)
{
    const int*   inputs     = (const int*)  d_in[0];
    const float* input_mask = (const float*)d_in[1];
    const float* emb        = (const float*)d_in[2];
    const float* conv_w     = (const float*)d_in[3];
    const float* conv_b     = (const float*)d_in[4];
    const float* pos        = (const float*)d_in[5];
    const float* cls        = (const float*)d_in[6];
    const float* Wq         = (const float*)d_in[7];
    const float* bq         = (const float*)d_in[8];
    const float* Wk         = (const float*)d_in[9];
    const float* bk         = (const float*)d_in[10];
    const float* Wv         = (const float*)d_in[11];
    const float* bv         = (const float*)d_in[12];
    const float* Wo         = (const float*)d_in[13];
    const float* bo         = (const float*)d_in[14];
    const float* ln1_s      = (const float*)d_in[15];
    const float* ln1_b      = (const float*)d_in[16];
    const float* ln2_s      = (const float*)d_in[17];
    const float* ln2_b      = (const float*)d_in[18];
    const float* W1         = (const float*)d_in[19];
    const float* b1         = (const float*)d_in[20];
    const float* W2         = (const float*)d_in[21];
    const float* b2         = (const float*)d_in[22];
    const float* lnf_s      = (const float*)d_in[23];
    const float* lnf_b      = (const float*)d_in[24];
    const float* out_w      = (const float*)d_in[25];
    const float* out_b      = (const float*)d_in[26];
    float* out              = (float*)d_out;

    float *x, *q, *k, *v, *tb, *hbuf, *ybuf, *wct, *kv, *ksum, *z, *len;
    cudaGetSymbolAddress((void**)&x,    g_x);
    cudaGetSymbolAddress((void**)&q,    g_q);
    cudaGetSymbolAddress((void**)&k,    g_k);
    cudaGetSymbolAddress((void**)&v,    g_v);
    cudaGetSymbolAddress((void**)&tb,   g_t);
    cudaGetSymbolAddress((void**)&hbuf, g_h);
    cudaGetSymbolAddress((void**)&ybuf, g_y);
    cudaGetSymbolAddress((void**)&wct,  g_wct);
    cudaGetSymbolAddress((void**)&kv,   g_kv);
    cudaGetSymbolAddress((void**)&ksum, g_ksum);
    cudaGetSymbolAddress((void**)&z,    g_z);
    cudaGetSymbolAddress((void**)&len,  g_len);

    // ---- embedding conv (gather fused into GEMM A-load) ----
    {
        size_t n1 = (size_t)KCONV * DD;
        transpose_convw_kernel<<<(unsigned)((n1 + 255) / 256), 256>>>(conv_w, wct);
        launch_gemm_gather(inputs, emb, wct, ybuf, MPATCH, DD, KCONV);
        size_t n3 = (size_t)MTOK * DD;
        assemble_x_kernel<<<(unsigned)((n3 + 255) / 256), 256>>>(ybuf, cls, pos, conv_b, x);
        lengths_kernel<<<BB, 256>>>(input_mask, len);
    }

    // ---- transformer layers ----
    for (int i = 0; i < NLAYER; i++) {
        const float* Wqi = Wq + (size_t)i * DD * DD;
        const float* Wki = Wk + (size_t)i * DD * DD;
        const float* Wvi = Wv + (size_t)i * DD * DD;
        const float* Woi = Wo + (size_t)i * DD * DD;
        const float* W1i = W1 + (size_t)i * DD * FFD;
        const float* W2i = W2 + (size_t)i * FFD * DD;

        launch_gemm_plain(x, Wqi, q, MPAD, DD, DD);
        launch_gemm_plain(x, Wki, k, MPAD, DD, DD);
        launch_gemm_plain(x, Wvi, v, MPAD, DD, DD);

        {
            size_t n = (size_t)MTOK * HH * 32;
            rope_feat_kernel<<<(unsigned)((n + 255) / 256), 256>>>(q, k, bq + i * DD, bk + i * DD, len);
        }
        kv_ksum_kernel<<<BB * HH, 256>>>(k, v, bv + i * DD, kv, ksum);
        {
            size_t n = (size_t)MTOK * HH * 32;
            z_kernel<<<(unsigned)((n + 255) / 256), 256>>>(q, ksum, z);
        }
        attn_kernel<<<BB * HH, 256>>>(q, kv, z, tb);   // tb = attn (b,s,h,m)

        launch_gemm_plain(tb, Woi, v, MPAD, DD, DD);   // reuse v as Wo output
        ln_kernel<true><<<MTOK, 256>>>(v, bo + i * DD, x, ln1_s + i * DD, ln1_b + i * DD);

        launch_gemm_plain(x, W1i, hbuf, MPAD, FFD, DD);
        launch_gemm_gelu(hbuf, W2i, tb, MPAD, DD, FFD, b1 + i * FFD);
        ln_kernel<true><<<MTOK, 256>>>(tb, b2 + i * DD, x, ln2_s + i * DD, ln2_b + i * DD);
    }

    // ---- final LN + head ----
    ln_kernel<false><<<MTOK, 256>>>(nullptr, nullptr, x, lnf_s, lnf_b);
    head_kernel<<<1, 128>>>(x, out_w, out_b, out);
}